// round 1
// baseline (speedup 1.0000x reference)
#include <cuda_runtime.h>

// Problem constants
#define BB    256
#define HH    512
#define G4    2048
#define SRCT  512
#define INP   64
#define TGTT  96

// Kernel config
#define NBLK  128
#define NTHR  256
#define KC    32

// ---------------- device globals (scratch; no allocations allowed) ----------
static __device__ float g_h[2][2][BB * HH];   // [layer][parity][b*H+u]
static __device__ float g_c[2][BB * HH];      // [layer][b*H+u]
static __device__ float g_x[BB];              // decoder scalar input
static __device__ float g_fc[BB * HH];        // fc hidden
static __device__ unsigned g_count;
static __device__ volatile unsigned g_sense;

struct SM {
    float hs[KC][64];
    float ws[KC][64];
};

// ---------------- helpers ---------------------------------------------------
__device__ __forceinline__ float sigm(float x) {
    return 1.0f / (1.0f + __expf(-x));
}
__device__ __forceinline__ float tanh_f(float x) {
    return 2.0f / (1.0f + __expf(-2.0f * x)) - 1.0f;
}

// grid-wide barrier: monotonic generation counter (reset by prologue kernel)
__device__ __forceinline__ void gsync() {
    __threadfence();
    __syncthreads();
    if (threadIdx.x == 0) {
        unsigned a = atomicAdd(&g_count, 1u);
        unsigned target = a / NBLK + 1u;
        if ((a % NBLK) == (NBLK - 1)) {
            __threadfence();
            g_sense = target;
        } else {
            while (g_sense < target) { __nanosleep(64); }
        }
        __threadfence();
    }
    __syncthreads();
}

template <bool CG, bool RELU>
__device__ __forceinline__ void ldx8(float* r, const float* p) {
    float4 a, b;
    if (CG) {
        a = __ldcg((const float4*)p);
        b = __ldcg(((const float4*)p) + 1);
    } else {
        a = __ldg((const float4*)p);
        b = __ldg(((const float4*)p) + 1);
    }
    if (RELU) {
        a.x = fmaxf(a.x, 0.f); a.y = fmaxf(a.y, 0.f);
        a.z = fmaxf(a.z, 0.f); a.w = fmaxf(a.w, 0.f);
        b.x = fmaxf(b.x, 0.f); b.y = fmaxf(b.y, 0.f);
        b.z = fmaxf(b.z, 0.f); b.w = fmaxf(b.w, 0.f);
    }
    r[0] = a.x; r[1] = a.y; r[2] = a.z; r[3] = a.w;
    r[4] = b.x; r[5] = b.y; r[6] = b.z; r[7] = b.w;
}

__device__ __forceinline__ void ldw8(float* r, const float* p) {
    float4 a = __ldg((const float4*)p);
    float4 b = __ldg(((const float4*)p) + 1);
    r[0] = a.x; r[1] = a.y; r[2] = a.z; r[3] = a.w;
    r[4] = b.x; r[5] = b.y; r[6] = b.z; r[7] = b.w;
}

// Accumulate acc[4 b-rows][4 cols] += X_tile * W_tile^T over nt k-tiles.
// px: thread's X row pointer (row b_base+lrow, + lseg), pw: W row pointer.
template <bool CG, bool RELU>
__device__ __forceinline__ void mm_accum(float (&acc)[4][4], SM& sm,
                                         const float* px, const float* pw,
                                         int nt, int tx, int ty,
                                         int lrow, int lseg) {
    float rx[8], rw[8];
    ldx8<CG, RELU>(rx, px);
    ldw8(rw, pw);
    for (int kt = 0; kt < nt; kt++) {
        __syncthreads();
#pragma unroll
        for (int i = 0; i < 8; i++) {
            sm.hs[lseg + i][lrow] = rx[i];
            sm.ws[lseg + i][lrow] = rw[i];
        }
        __syncthreads();
        if (kt + 1 < nt) {
            ldx8<CG, RELU>(rx, px + (kt + 1) * KC);
            ldw8(rw, pw + (kt + 1) * KC);
        }
        const float4* h4 = reinterpret_cast<const float4*>(&sm.hs[0][0]);
        const float4* w4 = reinterpret_cast<const float4*>(&sm.ws[0][0]);
#pragma unroll
        for (int kk = 0; kk < KC; kk++) {
            float4 a = h4[kk * 16 + ty];
            float4 w = w4[kk * 16 + tx];
            acc[0][0] += a.x * w.x; acc[0][1] += a.x * w.y;
            acc[0][2] += a.x * w.z; acc[0][3] += a.x * w.w;
            acc[1][0] += a.y * w.x; acc[1][1] += a.y * w.y;
            acc[1][2] += a.y * w.z; acc[1][3] += a.y * w.w;
            acc[2][0] += a.z * w.x; acc[2][1] += a.z * w.y;
            acc[2][2] += a.z * w.z; acc[2][3] += a.z * w.w;
            acc[3][0] += a.w * w.x; acc[3][1] += a.w * w.y;
            acc[3][2] += a.w * w.z; acc[3][3] += a.w * w.w;
        }
    }
}

// One LSTM layer step for this block's tile (64 b-rows x 16 cells x 4 gates).
// Kin==1 => scalar input from g_x. xcg selects .cg loads for the x operand.
__device__ __forceinline__ void lstm_layer(SM& sm,
                                           const float* xbase, long xld,
                                           int Kin, bool xcg,
                                           const float* Wih, const float* Whh,
                                           const float* bih, const float* bhh,
                                           const float* hprev, float* cbuf,
                                           float* hnext,
                                           int b_base, int u_base,
                                           int tx, int ty, int lrow, int lseg) {
    float acc[4][4];
    const int u = u_base + tx;
#pragma unroll
    for (int g = 0; g < 4; g++) {
        float bbias = __ldg(bih + g * HH + u) + __ldg(bhh + g * HH + u);
        acc[0][g] = bbias; acc[1][g] = bbias;
        acc[2][g] = bbias; acc[3][g] = bbias;
    }
    const int wg = lrow & 3;
    const int wu = u_base + (lrow >> 2);

    if (Kin >= KC) {
        const float* px = xbase + (long)(b_base + lrow) * xld + lseg;
        const float* pw = Wih + (long)(wg * HH + wu) * Kin + lseg;
        if (xcg) mm_accum<true, false>(acc, sm, px, pw, Kin / KC, tx, ty, lrow, lseg);
        else     mm_accum<false, false>(acc, sm, px, pw, Kin / KC, tx, ty, lrow, lseg);
    } else if (Kin == 1) {
        float wv[4];
#pragma unroll
        for (int g = 0; g < 4; g++) wv[g] = __ldg(Wih + g * HH + u);
#pragma unroll
        for (int i = 0; i < 4; i++) {
            float xv = __ldcg(&g_x[b_base + ty * 4 + i]);
#pragma unroll
            for (int g = 0; g < 4; g++) acc[i][g] += xv * wv[g];
        }
    }

    {   // recurrent part: h_prev @ Whh^T
        const float* px = hprev + (long)(b_base + lrow) * HH + lseg;
        const float* pw = Whh + (long)(wg * HH + wu) * HH + lseg;
        mm_accum<true, false>(acc, sm, px, pw, HH / KC, tx, ty, lrow, lseg);
    }

#pragma unroll
    for (int i = 0; i < 4; i++) {
        const int b = b_base + ty * 4 + i;
        const long o = (long)b * HH + u;
        float ig = sigm(acc[i][0]);
        float fg = sigm(acc[i][1]);
        float gv = tanh_f(acc[i][2]);
        float og = sigm(acc[i][3]);
        float c = fg * __ldcg(cbuf + o) + ig * gv;
        __stcg(cbuf + o, c);
        __stcg(hnext + o, og * tanh_f(c));
    }
}

// ---------------- prologue: reset barrier + states --------------------------
__global__ void reset_kernel(const float* __restrict__ tgt) {
    long idx = (long)blockIdx.x * blockDim.x + threadIdx.x;
    long stride = (long)gridDim.x * blockDim.x;
    float* hp = &g_h[0][0][0];
    for (long i = idx; i < 2L * 2 * BB * HH; i += stride) hp[i] = 0.f;
    float* cp = &g_c[0][0];
    for (long i = idx; i < 2L * BB * HH; i += stride) cp[i] = 0.f;
    if (idx < BB) g_x[idx] = tgt[idx * TGTT];  // tgt[:,0]
    if (idx == 0) { g_count = 0u; g_sense = 0u; }
}

// ---------------- main persistent kernel ------------------------------------
__global__ __launch_bounds__(NTHR, 1) void seq2seq_kernel(
    const float* __restrict__ src, const float* __restrict__ tgt,
    const float* __restrict__ eWih0, const float* __restrict__ eWhh0,
    const float* __restrict__ ebih0, const float* __restrict__ ebhh0,
    const float* __restrict__ dWih0, const float* __restrict__ dWhh0,
    const float* __restrict__ dbih0, const float* __restrict__ dbhh0,
    const float* __restrict__ eWih1, const float* __restrict__ eWhh1,
    const float* __restrict__ ebih1, const float* __restrict__ ebhh1,
    const float* __restrict__ dWih1, const float* __restrict__ dWhh1,
    const float* __restrict__ dbih1, const float* __restrict__ dbhh1,
    const float* __restrict__ fW0, const float* __restrict__ fb0,
    const float* __restrict__ fW1, const float* __restrict__ fb1,
    float* __restrict__ out) {
    __shared__ SM sm;

    const int tid = threadIdx.x;
    const int tx = tid & 15;
    const int ty = tid >> 4;
    const int lrow = tid & 63;
    const int lseg = (tid >> 6) * 8;

    const int bt = blockIdx.x >> 5;          // 0..3
    const int jt = blockIdx.x & 31;          // 0..31
    const int b_base = bt * 64;
    const int u_base = jt * 16;

    int par = 0;

    // ---------------- encoder ----------------
    for (int t = 0; t < SRCT; t++) {
        // layer 0: x = src[:, t, :]  (row stride SRCT*INP)
        lstm_layer(sm, src + (long)t * INP, (long)SRCT * INP, INP, false,
                   eWih0, eWhh0, ebih0, ebhh0,
                   g_h[0][par], g_c[0], g_h[0][par ^ 1],
                   b_base, u_base, tx, ty, lrow, lseg);
        gsync();
        // layer 1: x = h0 (just written)
        lstm_layer(sm, g_h[0][par ^ 1], HH, HH, true,
                   eWih1, eWhh1, ebih1, ebhh1,
                   g_h[1][par], g_c[1], g_h[1][par ^ 1],
                   b_base, u_base, tx, ty, lrow, lseg);
        gsync();
        par ^= 1;
    }

    // ---------------- decoder ----------------
    for (int t = 0; t < TGTT; t++) {
        // layer 0: scalar input from g_x
        lstm_layer(sm, nullptr, 0, 1, true,
                   dWih0, dWhh0, dbih0, dbhh0,
                   g_h[0][par], g_c[0], g_h[0][par ^ 1],
                   b_base, u_base, tx, ty, lrow, lseg);
        gsync();
        // layer 1
        lstm_layer(sm, g_h[0][par ^ 1], HH, HH, true,
                   dWih1, dWhh1, dbih1, dbhh1,
                   g_h[1][par], g_c[1], g_h[1][par ^ 1],
                   b_base, u_base, tx, ty, lrow, lseg);
        gsync();

        // fc0: g_fc = relu( relu(h1) @ W0^T + b0 ), on blocks 0..31
        if (blockIdx.x < 32) {
            const int bb2 = (blockIdx.x >> 3) * 64;
            const int jb = (blockIdx.x & 7) * 64;
            float acc[4][4];
#pragma unroll
            for (int q = 0; q < 4; q++) {
                float bbias = __ldg(fb0 + jb + tx * 4 + q);
                acc[0][q] = bbias; acc[1][q] = bbias;
                acc[2][q] = bbias; acc[3][q] = bbias;
            }
            const float* px = g_h[1][par ^ 1] + (long)(bb2 + lrow) * HH + lseg;
            const float* pw = fW0 + (long)(jb + lrow) * HH + lseg;
            mm_accum<true, true>(acc, sm, px, pw, HH / KC, tx, ty, lrow, lseg);
#pragma unroll
            for (int i = 0; i < 4; i++) {
                const int b = bb2 + ty * 4 + i;
#pragma unroll
                for (int q = 0; q < 4; q++) {
                    const int j = jb + tx * 4 + q;
                    __stcg(g_fc + (long)b * HH + j, fmaxf(acc[i][q], 0.f));
                }
            }
        }
        gsync();

        // fc1: out[b] = g_fc[b] . W1 + b1 ; becomes next decoder input
        if (blockIdx.x == 0) {
            const int b = tid;  // 256 threads = 256 batch rows
            const float4* tp = (const float4*)(g_fc + (long)b * HH);
            const float4* wp = (const float4*)fW1;
            float s0 = 0.f, s1 = 0.f, s2 = 0.f, s3 = 0.f;
#pragma unroll 8
            for (int k = 0; k < HH / 4; k++) {
                float4 v = __ldcg(tp + k);
                float4 w = __ldg(wp + k);
                s0 += v.x * w.x; s1 += v.y * w.y;
                s2 += v.z * w.z; s3 += v.w * w.w;
            }
            float o = (s0 + s1) + (s2 + s3) + __ldg(fb1);
            out[(long)b * TGTT + t] = o;
            __stcg(&g_x[b], o);
        }
        gsync();
        par ^= 1;
    }
}

// ---------------- launch ----------------------------------------------------
extern "C" void kernel_launch(void* const* d_in, const int* in_sizes, int n_in,
                              void* d_out, int out_size) {
    const float* src   = (const float*)d_in[0];
    const float* tgt   = (const float*)d_in[1];
    const float* eWih0 = (const float*)d_in[2];
    const float* eWhh0 = (const float*)d_in[3];
    const float* ebih0 = (const float*)d_in[4];
    const float* ebhh0 = (const float*)d_in[5];
    const float* dWih0 = (const float*)d_in[6];
    const float* dWhh0 = (const float*)d_in[7];
    const float* dbih0 = (const float*)d_in[8];
    const float* dbhh0 = (const float*)d_in[9];
    const float* eWih1 = (const float*)d_in[10];
    const float* eWhh1 = (const float*)d_in[11];
    const float* ebih1 = (const float*)d_in[12];
    const float* ebhh1 = (const float*)d_in[13];
    const float* dWih1 = (const float*)d_in[14];
    const float* dWhh1 = (const float*)d_in[15];
    const float* dbih1 = (const float*)d_in[16];
    const float* dbhh1 = (const float*)d_in[17];
    const float* fW0   = (const float*)d_in[18];
    const float* fb0   = (const float*)d_in[19];
    const float* fW1   = (const float*)d_in[20];
    const float* fb1   = (const float*)d_in[21];
    float* out = (float*)d_out;

    reset_kernel<<<512, 256>>>(tgt);
    seq2seq_kernel<<<NBLK, NTHR>>>(src, tgt,
                                   eWih0, eWhh0, ebih0, ebhh0,
                                   dWih0, dWhh0, dbih0, dbhh0,
                                   eWih1, eWhh1, ebih1, ebhh1,
                                   dWih1, dWhh1, dbih1, dbhh1,
                                   fW0, fb0, fW1, fb1, out);
}